// round 1
// baseline (speedup 1.0000x reference)
#include <cuda_runtime.h>
#include <math.h>
#include <stdint.h>

// ----------------------------------------------------------------------------
// GaussianScene preprocess + stable depth sort + gather
//   out[N][21] = packed[argsort_stable(depth_key)]
// ----------------------------------------------------------------------------

#define N_MAX   2100000
#define NCOLS   21
#define SORT_THREADS 256
#define SORT_EPT     32
#define SORT_TILE    (SORT_THREADS * SORT_EPT)   // 8192
#define MAX_NB  ((N_MAX + SORT_TILE - 1) / SORT_TILE + 1)

// static scratch (allocation is forbidden; __device__ globals are the sanctioned path)
__device__ float    g_packed[(size_t)N_MAX * NCOLS];
__device__ unsigned g_keyA[N_MAX];
__device__ unsigned g_keyB[N_MAX];
__device__ unsigned g_valA[N_MAX];
__device__ unsigned g_valB[N_MAX];
__device__ unsigned g_hist[256 * MAX_NB];
__device__ unsigned g_binTotal[256];
__device__ unsigned g_binBase[256];

// float -> order-preserving uint
__device__ __forceinline__ unsigned f2u(float f) {
    unsigned u = __float_as_uint(f);
    return (u & 0x80000000u) ? ~u : (u | 0x80000000u);
}

// ----------------------------------------------------------------------------
// 1) per-point preprocess: compute 21 packed values + sort key
// ----------------------------------------------------------------------------
__global__ __launch_bounds__(256)
void prep_kernel(const float* __restrict__ pts,
                 const float* __restrict__ cols,
                 const float* __restrict__ opa,
                 const float* __restrict__ scl,
                 const float* __restrict__ quat,
                 const float* __restrict__ V,     // world2view 4x4 row-major
                 const float* __restrict__ F,     // full_proj 4x4 row-major
                 const float* __restrict__ tanxp,
                 const float* __restrict__ tanyp,
                 const float* __restrict__ fxp,
                 const float* __restrict__ fyp,
                 const int*   __restrict__ wptr,
                 const int*   __restrict__ hptr,
                 int n)
{
    int i = blockIdx.x * blockDim.x + threadIdx.x;
    if (i >= n) return;

    float tanX = tanxp[0], tanY = tanyp[0];
    float fx = fxp[0], fy = fyp[0];
    int wi = wptr[0], hi = hptr[0];
    float Wd = (wi > 0 && wi < 1000000) ? (float)wi : __int_as_float(wi);
    float Hd = (hi > 0 && hi < 1000000) ? (float)hi : __int_as_float(hi);

    float px_ = pts[3*i+0], py_ = pts[3*i+1], pz_ = pts[3*i+2];

    // quaternion -> rotation
    float qw = quat[4*i+0], qx = quat[4*i+1], qy = quat[4*i+2], qz = quat[4*i+3];
    float qn = rsqrtf(qw*qw + qx*qx + qy*qy + qz*qz);
    qw *= qn; qx *= qn; qy *= qn; qz *= qn;
    float R00 = 1.f - 2.f*(qy*qy + qz*qz);
    float R01 = 2.f*(qx*qy - qw*qz);
    float R02 = 2.f*(qx*qz + qw*qy);
    float R10 = 2.f*(qx*qy + qw*qz);
    float R11 = 1.f - 2.f*(qx*qx + qz*qz);
    float R12 = 2.f*(qy*qz - qw*qx);
    float R20 = 2.f*(qx*qz - qw*qy);
    float R21 = 2.f*(qy*qz + qw*qx);
    float R22 = 1.f - 2.f*(qx*qx + qy*qy);

    float s0 = scl[3*i+0], s1 = scl[3*i+1], s2 = scl[3*i+2];
    // M = R * diag(s) (column scaling), C = M M^T (symmetric)
    float M00 = R00*s0, M01 = R01*s1, M02 = R02*s2;
    float M10 = R10*s0, M11 = R11*s1, M12 = R12*s2;
    float M20 = R20*s0, M21 = R21*s1, M22 = R22*s2;
    float C00 = M00*M00 + M01*M01 + M02*M02;
    float C01 = M00*M10 + M01*M11 + M02*M12;
    float C02 = M00*M20 + M01*M21 + M02*M22;
    float C11 = M10*M10 + M11*M11 + M12*M12;
    float C12 = M10*M20 + M11*M21 + M12*M22;
    float C22 = M20*M20 + M21*M21 + M22*M22;

    // pview = [x y z 1] @ V (row-vector)
    float pvx = px_*V[0] + py_*V[4] + pz_*V[8]  + V[12];
    float pvy = px_*V[1] + py_*V[5] + pz_*V[9]  + V[13];
    float pvz = px_*V[2] + py_*V[6] + pz_*V[10] + V[14];
    float zview = pvz;
    bool in_view = (zview >= 0.2f);

    // pclip = [x y z 1] @ F
    float cx = px_*F[0] + py_*F[4] + pz_*F[8]  + F[12];
    float cy = px_*F[1] + py_*F[5] + pz_*F[9]  + F[13];
    float cw = px_*F[3] + py_*F[7] + pz_*F[11] + F[15];
    float ndx = cx / cw;
    float ndy = cy / cw;
    float px = ((ndx + 1.f) * Wd - 1.f) * 0.5f;
    float py = ((ndy + 1.f) * Hd - 1.f) * 0.5f;

    float limx = 1.3f * tanX, limy = 1.3f * tanY;
    float xc = fminf(fmaxf(pvx / zview, -limx), limx) * zview;
    float yc = fminf(fmaxf(pvy / zview, -limy), limy) * zview;
    float z2 = zview * zview;

    float J00 = fx / zview;
    float J02 = -(fx * xc) / z2;
    float J11 = fy / zview;
    float J12 = -(fy * yc) / z2;

    // T = J @ W, W = V[:3,:3]^T => T[i][k] = sum_j J[i][j] * V[k][j]
    float T00 = J00*V[0] + J02*V[2];
    float T01 = J00*V[4] + J02*V[6];
    float T02 = J00*V[8] + J02*V[10];
    float T10 = J11*V[1] + J12*V[2];
    float T11 = J11*V[5] + J12*V[6];
    float T12 = J11*V[9] + J12*V[10];

    // cov2d = T C T^T (take 2x2)
    float a00 = T00*C00 + T01*C01 + T02*C02;
    float a01 = T00*C01 + T01*C11 + T02*C12;
    float a02 = T00*C02 + T01*C12 + T02*C22;
    float a10 = T10*C00 + T11*C01 + T12*C02;
    float a11 = T10*C01 + T11*C11 + T12*C12;
    float a12 = T10*C02 + T11*C12 + T12*C22;

    float c00 = a00*T00 + a01*T01 + a02*T02;
    float c01 = a00*T10 + a01*T11 + a02*T12;
    float c10 = a10*T00 + a11*T01 + a12*T02;
    float c11 = a10*T10 + a11*T11 + a12*T12;

    float det = c00*c11 - c01*c10;
    float det_safe = (fabsf(det) < 1e-6f) ? 1e-6f : det;
    float ic0 =  c11 / det_safe;
    float ic1 = -c01 / det_safe;
    float ic2 = -c10 / det_safe;
    float ic3 =  c00 / det_safe;

    float mid = 0.5f * (c00 + c11);
    float inter = fmaxf(mid*mid - det, 0.1f);
    float lam = mid + sqrtf(inter);
    float radius = ceilf(3.0f * sqrtf(fmaxf(lam, 0.f)));
    float min_x = floorf(px - radius);
    float min_y = floorf(py - radius);
    float max_x = ceilf(px + radius);
    float max_y = ceilf(py + radius);

    // stable sigmoid
    float o = opa[i];
    float sig;
    if (o >= 0.f) { sig = 1.f / (1.f + expf(-o)); }
    else          { float e = expf(o); sig = e / (1.f + e); }

    float* dst = g_packed + (size_t)i * NCOLS;
    dst[0]  = px;     dst[1]  = py;     dst[2]  = zview;
    dst[3]  = c00;    dst[4]  = c01;    dst[5]  = c10;    dst[6] = c11;
    dst[7]  = ic0;    dst[8]  = ic1;    dst[9]  = ic2;    dst[10] = ic3;
    dst[11] = radius;
    dst[12] = min_x;  dst[13] = min_y;  dst[14] = max_x;  dst[15] = max_y;
    dst[16] = cols[3*i+0]; dst[17] = cols[3*i+1]; dst[18] = cols[3*i+2];
    dst[19] = sig;
    dst[20] = in_view ? 1.f : 0.f;

    float dkey = in_view ? zview : __int_as_float(0x7f800000);
    g_keyA[i] = f2u(dkey);
    g_valA[i] = (unsigned)i;
}

// ----------------------------------------------------------------------------
// 2) radix sort (4 x 8-bit LSD, stable)
// ----------------------------------------------------------------------------
__global__ __launch_bounds__(SORT_THREADS)
void hist_kernel(const unsigned* __restrict__ keys, int n, int shift, int nb)
{
    __shared__ unsigned sh[256];
    sh[threadIdx.x] = 0;
    __syncthreads();
    int base = blockIdx.x * SORT_TILE;
    #pragma unroll 4
    for (int r = 0; r < SORT_EPT; r++) {
        int idx = base + r * SORT_THREADS + threadIdx.x;
        if (idx < n) atomicAdd(&sh[(keys[idx] >> shift) & 255u], 1u);
    }
    __syncthreads();
    g_hist[threadIdx.x * nb + blockIdx.x] = sh[threadIdx.x];
}

// per-bin exclusive scan over blocks (grid = 256, one block per bin)
__global__ __launch_bounds__(256)
void scan_bins_kernel(int nb)
{
    __shared__ unsigned s[256];
    int bin = blockIdx.x;
    unsigned carry = 0;
    for (int start = 0; start < nb; start += 256) {
        int i = start + threadIdx.x;
        unsigned v = (i < nb) ? g_hist[bin * nb + i] : 0u;
        s[threadIdx.x] = v;
        __syncthreads();
        for (int off = 1; off < 256; off <<= 1) {
            unsigned t = (threadIdx.x >= off) ? s[threadIdx.x - off] : 0u;
            __syncthreads();
            s[threadIdx.x] += t;
            __syncthreads();
        }
        if (i < nb) g_hist[bin * nb + i] = carry + s[threadIdx.x] - v;
        unsigned tot = s[255];
        __syncthreads();
        carry += tot;
    }
    if (threadIdx.x == 0) g_binTotal[bin] = carry;
}

// exclusive scan of 256 bin totals (1 block)
__global__ __launch_bounds__(256)
void scan_total_kernel()
{
    __shared__ unsigned s[256];
    unsigned v = g_binTotal[threadIdx.x];
    s[threadIdx.x] = v;
    __syncthreads();
    for (int off = 1; off < 256; off <<= 1) {
        unsigned t = (threadIdx.x >= off) ? s[threadIdx.x - off] : 0u;
        __syncthreads();
        s[threadIdx.x] += t;
        __syncthreads();
    }
    g_binBase[threadIdx.x] = s[threadIdx.x] - v;
}

// stable scatter: warp multi-split via match_any + ordered cross-warp prefix
__global__ __launch_bounds__(SORT_THREADS)
void scatter_kernel(const unsigned* __restrict__ kin,
                    const unsigned* __restrict__ vin,
                    unsigned* __restrict__ kout,
                    unsigned* __restrict__ vout,
                    int n, int shift, int nb)
{
    __shared__ unsigned       sGlob[256];
    __shared__ unsigned       sBase[256];
    __shared__ unsigned short sCnt[8][256];
    __shared__ unsigned short sPre[8][256];

    int tid = threadIdx.x, warp = tid >> 5, lane = tid & 31;
    sGlob[tid] = g_binBase[tid] + g_hist[tid * nb + blockIdx.x];
    sBase[tid] = 0;
    int base = blockIdx.x * SORT_TILE;
    unsigned ltmask = (1u << lane) - 1u;

    for (int r = 0; r < SORT_EPT; r++) {
        #pragma unroll
        for (int w = 0; w < 8; w++) sCnt[w][tid] = 0;
        __syncthreads();

        int idx = base + r * SORT_THREADS + tid;
        bool valid = (idx < n);
        unsigned key = 0, val = 0, digit = 0;
        if (valid) { key = kin[idx]; val = vin[idx]; digit = (key >> shift) & 255u; }

        unsigned vm    = __ballot_sync(0xffffffffu, valid);
        unsigned peers = __match_any_sync(0xffffffffu, digit) & vm;
        unsigned rank  = __popc(peers & ltmask);
        if (valid && rank == 0) sCnt[warp][digit] = (unsigned short)__popc(peers);
        __syncthreads();

        // one thread per bin: ordered prefix over the 8 warps
        {
            unsigned acc = sBase[tid];
            #pragma unroll
            for (int w = 0; w < 8; w++) {
                unsigned c = sCnt[w][tid];
                sPre[w][tid] = (unsigned short)acc;
                acc += c;
            }
            sBase[tid] = acc;
        }
        __syncthreads();

        if (valid) {
            unsigned pos = sGlob[digit] + (unsigned)sPre[warp][digit] + rank;
            kout[pos] = key;
            vout[pos] = val;
        }
        // next round's sCnt zeroing is ordered by the loop-top __syncthreads()
    }
}

// ----------------------------------------------------------------------------
// 3) gather: out[r] = packed[idx[r]]
// ----------------------------------------------------------------------------
__global__ __launch_bounds__(256)
void gather_kernel(float* __restrict__ out, int total)
{
    int j = blockIdx.x * blockDim.x + threadIdx.x;
    if (j >= total) return;
    unsigned uj = (unsigned)j;
    unsigned r = uj / 21u;
    unsigned c = uj - r * 21u;
    unsigned src = g_valA[r];
    out[j] = g_packed[(size_t)src * NCOLS + c];
}

// ----------------------------------------------------------------------------
extern "C" void kernel_launch(void* const* d_in, const int* in_sizes, int n_in,
                              void* d_out, int out_size)
{
    const float* pts  = (const float*)d_in[0];
    const float* cols = (const float*)d_in[1];
    const float* opa  = (const float*)d_in[2];
    const float* scl  = (const float*)d_in[3];
    const float* quat = (const float*)d_in[4];
    const float* V    = (const float*)d_in[5];
    const float* F    = (const float*)d_in[6];
    const float* tanx = (const float*)d_in[7];
    const float* tany = (const float*)d_in[8];
    const float* fx   = (const float*)d_in[9];
    const float* fy   = (const float*)d_in[10];
    const int*   wp   = (const int*)d_in[11];
    const int*   hp   = (const int*)d_in[12];
    float* out = (float*)d_out;

    int n = in_sizes[2];           // opacity has N elements
    if (n <= 0 || n > N_MAX) return;

    unsigned keyA_h, keyB_h;  // silence unused warnings pattern (not needed)
    (void)keyA_h; (void)keyB_h; (void)n_in; (void)out_size;

    int prep_blocks = (n + 255) / 256;
    prep_kernel<<<prep_blocks, 256>>>(pts, cols, opa, scl, quat, V, F,
                                      tanx, tany, fx, fy, wp, hp, n);

    int nb = (n + SORT_TILE - 1) / SORT_TILE;

    // resolve device pointers of the static buffers once (host-side address fetch
    // via symbol is not graph-hostile; cudaGetSymbolAddress is not an allocation)
    static unsigned *kA = nullptr, *kB = nullptr, *vA = nullptr, *vB = nullptr;
    if (!kA) {
        cudaGetSymbolAddress((void**)&kA, g_keyA);
        cudaGetSymbolAddress((void**)&kB, g_keyB);
        cudaGetSymbolAddress((void**)&vA, g_valA);
        cudaGetSymbolAddress((void**)&vB, g_valB);
    }

    unsigned* kin = kA;  unsigned* vin = vA;
    unsigned* kout = kB; unsigned* vout = vB;
    for (int p = 0; p < 4; p++) {
        int shift = p * 8;
        hist_kernel<<<nb, SORT_THREADS>>>(kin, n, shift, nb);
        scan_bins_kernel<<<256, 256>>>(nb);
        scan_total_kernel<<<1, 256>>>();
        scatter_kernel<<<nb, SORT_THREADS>>>(kin, vin, kout, vout, n, shift, nb);
        unsigned* tk = kin; kin = kout; kout = tk;
        unsigned* tv = vin; vin = vout; vout = tv;
    }
    // after 4 passes, sorted (key,val) are back in g_keyA/g_valA (kin == kA)

    int total = n * NCOLS;
    int gather_blocks = (total + 255) / 256;
    gather_kernel<<<gather_blocks, 256>>>(out, total);
}

// round 2
// speedup vs baseline: 1.3903x; 1.3903x over previous
#include <cuda_runtime.h>
#include <math.h>
#include <stdint.h>

// ----------------------------------------------------------------------------
// GaussianScene preprocess + stable depth radix sort + gather
//   out[N][21] = packed[argsort_stable(depth_key)]
// ----------------------------------------------------------------------------

#define N_MAX   2100000
#define NCOLS   21
#define SORT_THREADS 256
#define SORT_EPT     16
#define SORT_TILE    (SORT_THREADS * SORT_EPT)   // 4096
#define MAX_NB  ((N_MAX + SORT_TILE - 1) / SORT_TILE + 1)

// static scratch (allocation is forbidden; __device__ globals are the sanctioned path)
__device__ float    g_packed[(size_t)N_MAX * NCOLS];
__device__ unsigned g_keyA[N_MAX];
__device__ unsigned g_keyB[N_MAX];
__device__ unsigned g_valA[N_MAX];
__device__ unsigned g_valB[N_MAX];
__device__ unsigned g_hist[256 * MAX_NB];      // [digit][block] -> scanned in place
__device__ unsigned g_histRaw[(size_t)MAX_NB * 256]; // [block][digit] raw counts
__device__ unsigned g_binTotal[256];
__device__ unsigned g_binBase[256];

// float -> order-preserving uint
__device__ __forceinline__ unsigned f2u(float f) {
    unsigned u = __float_as_uint(f);
    return (u & 0x80000000u) ? ~u : (u | 0x80000000u);
}

// ----------------------------------------------------------------------------
// 1) per-point preprocess: compute 21 packed values + sort key
//    packed rows staged through shared memory for coalesced global writes
// ----------------------------------------------------------------------------
__global__ __launch_bounds__(256)
void prep_kernel(const float* __restrict__ pts,
                 const float* __restrict__ cols,
                 const float* __restrict__ opa,
                 const float* __restrict__ scl,
                 const float* __restrict__ quat,
                 const float* __restrict__ V,     // world2view 4x4 row-major
                 const float* __restrict__ F,     // full_proj 4x4 row-major
                 const float* __restrict__ tanxp,
                 const float* __restrict__ tanyp,
                 const float* __restrict__ fxp,
                 const float* __restrict__ fyp,
                 const int*   __restrict__ wptr,
                 const int*   __restrict__ hptr,
                 int n)
{
    __shared__ float st[256 * NCOLS];

    int i = blockIdx.x * blockDim.x + threadIdx.x;
    int li = (i < n) ? i : (n - 1);   // clamp loads; invalid rows never emitted

    float tanX = tanxp[0], tanY = tanyp[0];
    float fx = fxp[0], fy = fyp[0];
    int wi = wptr[0], hi = hptr[0];
    float Wd = (float)wi;
    float Hd = (float)hi;

    float px_ = pts[3*li+0], py_ = pts[3*li+1], pz_ = pts[3*li+2];

    // quaternion -> rotation
    float qw = quat[4*li+0], qx = quat[4*li+1], qy = quat[4*li+2], qz = quat[4*li+3];
    float qn = rsqrtf(qw*qw + qx*qx + qy*qy + qz*qz);
    qw *= qn; qx *= qn; qy *= qn; qz *= qn;
    float R00 = 1.f - 2.f*(qy*qy + qz*qz);
    float R01 = 2.f*(qx*qy - qw*qz);
    float R02 = 2.f*(qx*qz + qw*qy);
    float R10 = 2.f*(qx*qy + qw*qz);
    float R11 = 1.f - 2.f*(qx*qx + qz*qz);
    float R12 = 2.f*(qy*qz - qw*qx);
    float R20 = 2.f*(qx*qz - qw*qy);
    float R21 = 2.f*(qy*qz + qw*qx);
    float R22 = 1.f - 2.f*(qx*qx + qy*qy);

    float s0 = scl[3*li+0], s1 = scl[3*li+1], s2 = scl[3*li+2];
    // M = R * diag(s), C = M M^T (symmetric)
    float M00 = R00*s0, M01 = R01*s1, M02 = R02*s2;
    float M10 = R10*s0, M11 = R11*s1, M12 = R12*s2;
    float M20 = R20*s0, M21 = R21*s1, M22 = R22*s2;
    float C00 = M00*M00 + M01*M01 + M02*M02;
    float C01 = M00*M10 + M01*M11 + M02*M12;
    float C02 = M00*M20 + M01*M21 + M02*M22;
    float C11 = M10*M10 + M11*M11 + M12*M12;
    float C12 = M10*M20 + M11*M21 + M12*M22;
    float C22 = M20*M20 + M21*M21 + M22*M22;

    // pview = [x y z 1] @ V (row-vector convention)
    float pvx = px_*V[0] + py_*V[4] + pz_*V[8]  + V[12];
    float pvy = px_*V[1] + py_*V[5] + pz_*V[9]  + V[13];
    float pvz = px_*V[2] + py_*V[6] + pz_*V[10] + V[14];
    float zview = pvz;
    bool in_view = (zview >= 0.2f);

    // pclip = [x y z 1] @ F
    float cx = px_*F[0] + py_*F[4] + pz_*F[8]  + F[12];
    float cy = px_*F[1] + py_*F[5] + pz_*F[9]  + F[13];
    float cw = px_*F[3] + py_*F[7] + pz_*F[11] + F[15];
    float ndx = cx / cw;
    float ndy = cy / cw;
    float px = ((ndx + 1.f) * Wd - 1.f) * 0.5f;
    float py = ((ndy + 1.f) * Hd - 1.f) * 0.5f;

    float limx = 1.3f * tanX, limy = 1.3f * tanY;
    float xc = fminf(fmaxf(pvx / zview, -limx), limx) * zview;
    float yc = fminf(fmaxf(pvy / zview, -limy), limy) * zview;
    float z2 = zview * zview;

    float J00 = fx / zview;
    float J02 = -(fx * xc) / z2;
    float J11 = fy / zview;
    float J12 = -(fy * yc) / z2;

    // T = J @ W, W = V[:3,:3]^T => T[i][k] = sum_j J[i][j] * V[k][j]
    float T00 = J00*V[0] + J02*V[2];
    float T01 = J00*V[4] + J02*V[6];
    float T02 = J00*V[8] + J02*V[10];
    float T10 = J11*V[1] + J12*V[2];
    float T11 = J11*V[5] + J12*V[6];
    float T12 = J11*V[9] + J12*V[10];

    // cov2d = T C T^T (2x2)
    float a00 = T00*C00 + T01*C01 + T02*C02;
    float a01 = T00*C01 + T01*C11 + T02*C12;
    float a02 = T00*C02 + T01*C12 + T02*C22;
    float a10 = T10*C00 + T11*C01 + T12*C02;
    float a11 = T10*C01 + T11*C11 + T12*C12;
    float a12 = T10*C02 + T11*C12 + T12*C22;

    float c00 = a00*T00 + a01*T01 + a02*T02;
    float c01 = a00*T10 + a01*T11 + a02*T12;
    float c10 = a10*T00 + a11*T01 + a12*T02;
    float c11 = a10*T10 + a11*T11 + a12*T12;

    float det = c00*c11 - c01*c10;
    float det_safe = (fabsf(det) < 1e-6f) ? 1e-6f : det;
    float ic0 =  c11 / det_safe;
    float ic1 = -c01 / det_safe;
    float ic2 = -c10 / det_safe;
    float ic3 =  c00 / det_safe;

    float mid = 0.5f * (c00 + c11);
    float inter = fmaxf(mid*mid - det, 0.1f);
    float lam = mid + sqrtf(inter);
    float radius = ceilf(3.0f * sqrtf(fmaxf(lam, 0.f)));
    float min_x = floorf(px - radius);
    float min_y = floorf(py - radius);
    float max_x = ceilf(px + radius);
    float max_y = ceilf(py + radius);

    // stable sigmoid
    float o = opa[li];
    float sig;
    if (o >= 0.f) { sig = 1.f / (1.f + expf(-o)); }
    else          { float e = expf(o); sig = e / (1.f + e); }

    float* row = st + threadIdx.x * NCOLS;
    row[0]  = px;     row[1]  = py;     row[2]  = zview;
    row[3]  = c00;    row[4]  = c01;    row[5]  = c10;    row[6] = c11;
    row[7]  = ic0;    row[8]  = ic1;    row[9]  = ic2;    row[10] = ic3;
    row[11] = radius;
    row[12] = min_x;  row[13] = min_y;  row[14] = max_x;  row[15] = max_y;
    row[16] = cols[3*li+0]; row[17] = cols[3*li+1]; row[18] = cols[3*li+2];
    row[19] = sig;
    row[20] = in_view ? 1.f : 0.f;

    if (i < n) {
        float dkey = in_view ? zview : __int_as_float(0x7f800000);
        g_keyA[i] = f2u(dkey);
        g_valA[i] = (unsigned)i;
    }
    __syncthreads();

    // coalesced flush of staged rows
    size_t base = (size_t)blockIdx.x * 256 * NCOLS;
    int limit = n * NCOLS;
    for (int k = threadIdx.x; k < 256 * NCOLS; k += 256) {
        size_t g = base + k;
        if (g < (size_t)limit) g_packed[g] = st[k];
    }
}

// ----------------------------------------------------------------------------
// 2) radix sort (4 x 8-bit LSD, stable, shared-exchange scatter)
// ----------------------------------------------------------------------------
__global__ __launch_bounds__(SORT_THREADS)
void hist_kernel(const unsigned* __restrict__ keys, int n, int shift, int nb)
{
    __shared__ unsigned sh[256];
    sh[threadIdx.x] = 0;
    __syncthreads();
    int base = blockIdx.x * SORT_TILE;
    #pragma unroll 4
    for (int r = 0; r < SORT_EPT; r++) {
        int idx = base + r * SORT_THREADS + threadIdx.x;
        if (idx < n) atomicAdd(&sh[(keys[idx] >> shift) & 255u], 1u);
    }
    __syncthreads();
    unsigned c = sh[threadIdx.x];
    g_hist[threadIdx.x * nb + blockIdx.x] = c;                      // for scan
    g_histRaw[(size_t)blockIdx.x * 256 + threadIdx.x] = c;          // for scatter
}

// per-bin exclusive scan over blocks (grid = 256, one block per bin)
__global__ __launch_bounds__(256)
void scan_bins_kernel(int nb)
{
    __shared__ unsigned s[256];
    int bin = blockIdx.x;
    unsigned carry = 0;
    for (int start = 0; start < nb; start += 256) {
        int i = start + threadIdx.x;
        unsigned v = (i < nb) ? g_hist[bin * nb + i] : 0u;
        s[threadIdx.x] = v;
        __syncthreads();
        for (int off = 1; off < 256; off <<= 1) {
            unsigned t = (threadIdx.x >= off) ? s[threadIdx.x - off] : 0u;
            __syncthreads();
            s[threadIdx.x] += t;
            __syncthreads();
        }
        if (i < nb) g_hist[bin * nb + i] = carry + s[threadIdx.x] - v;
        unsigned tot = s[255];
        __syncthreads();
        carry += tot;
    }
    if (threadIdx.x == 0) g_binTotal[bin] = carry;
}

// exclusive scan of 256 bin totals (1 block)
__global__ __launch_bounds__(256)
void scan_total_kernel()
{
    __shared__ unsigned s[256];
    unsigned v = g_binTotal[threadIdx.x];
    s[threadIdx.x] = v;
    __syncthreads();
    for (int off = 1; off < 256; off <<= 1) {
        unsigned t = (threadIdx.x >= off) ? s[threadIdx.x - off] : 0u;
        __syncthreads();
        s[threadIdx.x] += t;
        __syncthreads();
    }
    g_binBase[threadIdx.x] = s[threadIdx.x] - v;
}

// stable scatter with shared-memory exchange:
//   rank -> place tile in block-sorted order in shared -> coalesced global emit
__global__ __launch_bounds__(SORT_THREADS)
void scatter_kernel(const unsigned* __restrict__ kin,
                    const unsigned* __restrict__ vin,
                    unsigned* __restrict__ kout,
                    unsigned* __restrict__ vout,
                    int n, int shift, int nb)
{
    __shared__ unsigned       sGlob[256];   // global base of this block's digit-d run
    __shared__ unsigned       sLoc[256];    // local exclusive start of digit-d run
    __shared__ unsigned       sBase[256];   // running local placement counter
    __shared__ unsigned       sScan[256];
    __shared__ unsigned short sCnt[8][256];
    __shared__ unsigned short sPre[8][256];
    __shared__ unsigned       sKey[SORT_TILE];
    __shared__ unsigned       sVal[SORT_TILE];

    int tid = threadIdx.x, warp = tid >> 5, lane = tid & 31;
    int base = blockIdx.x * SORT_TILE;
    int m = n - base; if (m > SORT_TILE) m = SORT_TILE;
    unsigned ltmask = (1u << lane) - 1u;

    // local digit-start offsets from raw per-block histogram
    unsigned cnt = g_histRaw[(size_t)blockIdx.x * 256 + tid];
    sScan[tid] = cnt;
    sGlob[tid] = g_binBase[tid] + g_hist[tid * nb + blockIdx.x];
    __syncthreads();
    for (int off = 1; off < 256; off <<= 1) {
        unsigned t = (tid >= off) ? sScan[tid - off] : 0u;
        __syncthreads();
        sScan[tid] += t;
        __syncthreads();
    }
    unsigned loc = sScan[tid] - cnt;
    sLoc[tid]  = loc;
    sBase[tid] = loc;
    __syncthreads();

    // ranking rounds: stable placement into shared tile
    for (int r = 0; r < SORT_EPT; r++) {
        #pragma unroll
        for (int w = 0; w < 8; w++) sCnt[w][tid] = 0;
        __syncthreads();

        int idx = base + r * SORT_THREADS + tid;
        bool valid = (idx < n);
        unsigned key = 0, val = 0, digit = 0;
        if (valid) { key = kin[idx]; val = vin[idx]; digit = (key >> shift) & 255u; }

        unsigned vm    = __ballot_sync(0xffffffffu, valid);
        unsigned peers = __match_any_sync(0xffffffffu, digit) & vm;
        unsigned rank  = __popc(peers & ltmask);
        if (valid && rank == 0) sCnt[warp][digit] = (unsigned short)__popc(peers);
        __syncthreads();

        // one thread per digit: ordered prefix over the 8 warps
        {
            unsigned acc = sBase[tid];
            #pragma unroll
            for (int w = 0; w < 8; w++) {
                unsigned c = sCnt[w][tid];
                sPre[w][tid] = (unsigned short)acc;
                acc += c;
            }
            sBase[tid] = acc;
        }
        __syncthreads();

        if (valid) {
            unsigned p = (unsigned)sPre[warp][digit] + rank;  // includes sLoc
            sKey[p] = key;
            sVal[p] = val;
        }
    }
    __syncthreads();

    // coalesced emit: digit runs are contiguous both locally and globally
    for (int j = tid; j < m; j += SORT_THREADS) {
        unsigned key = sKey[j];
        unsigned d = (key >> shift) & 255u;
        unsigned pos = sGlob[d] + ((unsigned)j - sLoc[d]);
        kout[pos] = key;
        vout[pos] = sVal[j];
    }
}

// ----------------------------------------------------------------------------
// 3) gather: out[r] = packed[idx[r]]
// ----------------------------------------------------------------------------
__global__ __launch_bounds__(256)
void gather_kernel(float* __restrict__ out, int total)
{
    int j = blockIdx.x * blockDim.x + threadIdx.x;
    if (j >= total) return;
    unsigned uj = (unsigned)j;
    unsigned r = uj / 21u;
    unsigned c = uj - r * 21u;
    unsigned src = g_valA[r];
    out[j] = g_packed[(size_t)src * NCOLS + c];
}

// ----------------------------------------------------------------------------
extern "C" void kernel_launch(void* const* d_in, const int* in_sizes, int n_in,
                              void* d_out, int out_size)
{
    const float* pts  = (const float*)d_in[0];
    const float* cols = (const float*)d_in[1];
    const float* opa  = (const float*)d_in[2];
    const float* scl  = (const float*)d_in[3];
    const float* quat = (const float*)d_in[4];
    const float* V    = (const float*)d_in[5];
    const float* F    = (const float*)d_in[6];
    const float* tanx = (const float*)d_in[7];
    const float* tany = (const float*)d_in[8];
    const float* fx   = (const float*)d_in[9];
    const float* fy   = (const float*)d_in[10];
    const int*   wp   = (const int*)d_in[11];
    const int*   hp   = (const int*)d_in[12];
    float* out = (float*)d_out;

    int n = in_sizes[2];           // opacity has N elements
    if (n <= 0 || n > N_MAX) return;
    (void)n_in; (void)out_size;

    int prep_blocks = (n + 255) / 256;
    prep_kernel<<<prep_blocks, 256>>>(pts, cols, opa, scl, quat, V, F,
                                      tanx, tany, fx, fy, wp, hp, n);

    int nb = (n + SORT_TILE - 1) / SORT_TILE;

    static unsigned *kA = nullptr, *kB = nullptr, *vA = nullptr, *vB = nullptr;
    if (!kA) {
        cudaGetSymbolAddress((void**)&kA, g_keyA);
        cudaGetSymbolAddress((void**)&kB, g_keyB);
        cudaGetSymbolAddress((void**)&vA, g_valA);
        cudaGetSymbolAddress((void**)&vB, g_valB);
    }

    unsigned* kin = kA;  unsigned* vin = vA;
    unsigned* kout = kB; unsigned* vout = vB;
    for (int p = 0; p < 4; p++) {
        int shift = p * 8;
        hist_kernel<<<nb, SORT_THREADS>>>(kin, n, shift, nb);
        scan_bins_kernel<<<256, 256>>>(nb);
        scan_total_kernel<<<1, 256>>>();
        scatter_kernel<<<nb, SORT_THREADS>>>(kin, vin, kout, vout, n, shift, nb);
        unsigned* tk = kin; kin = kout; kout = tk;
        unsigned* tv = vin; vin = vout; vout = tv;
    }
    // after 4 passes, sorted (key,val) are back in g_keyA/g_valA

    int total = n * NCOLS;
    int gather_blocks = (total + 255) / 256;
    gather_kernel<<<gather_blocks, 256>>>(out, total);
}

// round 3
// speedup vs baseline: 1.3988x; 1.0062x over previous
#include <cuda_runtime.h>
#include <math.h>
#include <stdint.h>

// ----------------------------------------------------------------------------
// GaussianScene preprocess + stable depth radix sort (onesweep) + gather
//   out[N][21] = packed[argsort_stable(depth_key)]
// ----------------------------------------------------------------------------

#define N_MAX   2100000
#define NCOLS   21
#define NPAD    24                     // padded row: 96B, sector aligned
#define SORT_THREADS 256
#define SORT_EPT     16
#define SORT_TILE    (SORT_THREADS * SORT_EPT)   // 4096
#define MAX_NB  ((N_MAX + SORT_TILE - 1) / SORT_TILE + 1)   // 513+

#define AGG_FLAG 0x40000000u
#define INC_FLAG 0x80000000u
#define VAL_MASK 0x3FFFFFFFu

// static scratch (allocation is forbidden; __device__ globals are the path)
__device__ float    g_packed[(size_t)N_MAX * NPAD];
__device__ unsigned g_keyA[N_MAX];
__device__ unsigned g_keyB[N_MAX];
__device__ unsigned g_valA[N_MAX];
__device__ unsigned g_valB[N_MAX];
__device__ unsigned g_lb[4 * MAX_NB * 256];   // lookback status words (memset 0)
__device__ unsigned g_gh4[4 * 256];           // global digit hists, all passes (memset 0)
__device__ unsigned g_base4[4 * 256];         // exclusive digit bases per pass

// float -> order-preserving uint
__device__ __forceinline__ unsigned f2u(float f) {
    unsigned u = __float_as_uint(f);
    return (u & 0x80000000u) ? ~u : (u | 0x80000000u);
}

// ----------------------------------------------------------------------------
// 1) per-point preprocess: 21 packed values (padded to 24) + sort key
// ----------------------------------------------------------------------------
__global__ __launch_bounds__(256)
void prep_kernel(const float* __restrict__ pts,
                 const float* __restrict__ cols,
                 const float* __restrict__ opa,
                 const float* __restrict__ scl,
                 const float* __restrict__ quat,
                 const float* __restrict__ V,     // world2view 4x4 row-major
                 const float* __restrict__ F,     // full_proj 4x4 row-major
                 const float* __restrict__ tanxp,
                 const float* __restrict__ tanyp,
                 const float* __restrict__ fxp,
                 const float* __restrict__ fyp,
                 const int*   __restrict__ wptr,
                 const int*   __restrict__ hptr,
                 int n)
{
    __shared__ float st[256 * NPAD];

    int i = blockIdx.x * blockDim.x + threadIdx.x;
    int li = (i < n) ? i : (n - 1);   // clamp loads; clamped rows never gathered

    float tanX = tanxp[0], tanY = tanyp[0];
    float fx = fxp[0], fy = fyp[0];
    float Wd = (float)wptr[0];
    float Hd = (float)hptr[0];

    float px_ = pts[3*li+0], py_ = pts[3*li+1], pz_ = pts[3*li+2];

    // quaternion -> rotation
    float qw = quat[4*li+0], qx = quat[4*li+1], qy = quat[4*li+2], qz = quat[4*li+3];
    float qn = rsqrtf(qw*qw + qx*qx + qy*qy + qz*qz);
    qw *= qn; qx *= qn; qy *= qn; qz *= qn;
    float R00 = 1.f - 2.f*(qy*qy + qz*qz);
    float R01 = 2.f*(qx*qy - qw*qz);
    float R02 = 2.f*(qx*qz + qw*qy);
    float R10 = 2.f*(qx*qy + qw*qz);
    float R11 = 1.f - 2.f*(qx*qx + qz*qz);
    float R12 = 2.f*(qy*qz - qw*qx);
    float R20 = 2.f*(qx*qz - qw*qy);
    float R21 = 2.f*(qy*qz + qw*qx);
    float R22 = 1.f - 2.f*(qx*qx + qy*qy);

    float s0 = scl[3*li+0], s1 = scl[3*li+1], s2 = scl[3*li+2];
    // M = R * diag(s), C = M M^T (symmetric)
    float M00 = R00*s0, M01 = R01*s1, M02 = R02*s2;
    float M10 = R10*s0, M11 = R11*s1, M12 = R12*s2;
    float M20 = R20*s0, M21 = R21*s1, M22 = R22*s2;
    float C00 = M00*M00 + M01*M01 + M02*M02;
    float C01 = M00*M10 + M01*M11 + M02*M12;
    float C02 = M00*M20 + M01*M21 + M02*M22;
    float C11 = M10*M10 + M11*M11 + M12*M12;
    float C12 = M10*M20 + M11*M21 + M12*M22;
    float C22 = M20*M20 + M21*M21 + M22*M22;

    // pview = [x y z 1] @ V
    float pvx = px_*V[0] + py_*V[4] + pz_*V[8]  + V[12];
    float pvy = px_*V[1] + py_*V[5] + pz_*V[9]  + V[13];
    float pvz = px_*V[2] + py_*V[6] + pz_*V[10] + V[14];
    float zview = pvz;
    bool in_view = (zview >= 0.2f);

    // pclip = [x y z 1] @ F
    float cx = px_*F[0] + py_*F[4] + pz_*F[8]  + F[12];
    float cy = px_*F[1] + py_*F[5] + pz_*F[9]  + F[13];
    float cw = px_*F[3] + py_*F[7] + pz_*F[11] + F[15];
    float ndx = cx / cw;
    float ndy = cy / cw;
    float px = ((ndx + 1.f) * Wd - 1.f) * 0.5f;
    float py = ((ndy + 1.f) * Hd - 1.f) * 0.5f;

    float limx = 1.3f * tanX, limy = 1.3f * tanY;
    float xc = fminf(fmaxf(pvx / zview, -limx), limx) * zview;
    float yc = fminf(fmaxf(pvy / zview, -limy), limy) * zview;
    float z2 = zview * zview;

    float J00 = fx / zview;
    float J02 = -(fx * xc) / z2;
    float J11 = fy / zview;
    float J12 = -(fy * yc) / z2;

    // T = J @ W, W = V[:3,:3]^T
    float T00 = J00*V[0] + J02*V[2];
    float T01 = J00*V[4] + J02*V[6];
    float T02 = J00*V[8] + J02*V[10];
    float T10 = J11*V[1] + J12*V[2];
    float T11 = J11*V[5] + J12*V[6];
    float T12 = J11*V[9] + J12*V[10];

    // cov2d = T C T^T (2x2)
    float a00 = T00*C00 + T01*C01 + T02*C02;
    float a01 = T00*C01 + T01*C11 + T02*C12;
    float a02 = T00*C02 + T01*C12 + T02*C22;
    float a10 = T10*C00 + T11*C01 + T12*C02;
    float a11 = T10*C01 + T11*C11 + T12*C12;
    float a12 = T10*C02 + T11*C12 + T12*C22;

    float c00 = a00*T00 + a01*T01 + a02*T02;
    float c01 = a00*T10 + a01*T11 + a02*T12;
    float c10 = a10*T00 + a11*T01 + a12*T02;
    float c11 = a10*T10 + a11*T11 + a12*T12;

    float det = c00*c11 - c01*c10;
    float det_safe = (fabsf(det) < 1e-6f) ? 1e-6f : det;
    float ic0 =  c11 / det_safe;
    float ic1 = -c01 / det_safe;
    float ic2 = -c10 / det_safe;
    float ic3 =  c00 / det_safe;

    float mid = 0.5f * (c00 + c11);
    float inter = fmaxf(mid*mid - det, 0.1f);
    float lam = mid + sqrtf(inter);
    float radius = ceilf(3.0f * sqrtf(fmaxf(lam, 0.f)));
    float min_x = floorf(px - radius);
    float min_y = floorf(py - radius);
    float max_x = ceilf(px + radius);
    float max_y = ceilf(py + radius);

    // stable sigmoid
    float o = opa[li];
    float sig;
    if (o >= 0.f) { sig = 1.f / (1.f + expf(-o)); }
    else          { float e = expf(o); sig = e / (1.f + e); }

    float* row = st + threadIdx.x * NPAD;
    row[0]  = px;     row[1]  = py;     row[2]  = zview;
    row[3]  = c00;    row[4]  = c01;    row[5]  = c10;    row[6] = c11;
    row[7]  = ic0;    row[8]  = ic1;    row[9]  = ic2;    row[10] = ic3;
    row[11] = radius;
    row[12] = min_x;  row[13] = min_y;  row[14] = max_x;  row[15] = max_y;
    row[16] = cols[3*li+0]; row[17] = cols[3*li+1]; row[18] = cols[3*li+2];
    row[19] = sig;
    row[20] = in_view ? 1.f : 0.f;
    row[21] = 0.f; row[22] = 0.f; row[23] = 0.f;

    if (i < n) {
        float dkey = in_view ? zview : __int_as_float(0x7f800000);
        g_keyA[i] = f2u(dkey);
        g_valA[i] = (unsigned)i;
    }
    __syncthreads();

    // coalesced flush of staged (padded) rows; stays within g_packed bounds
    size_t base = (size_t)blockIdx.x * 256 * NPAD;
    #pragma unroll 4
    for (int k = threadIdx.x; k < 256 * NPAD; k += 256)
        g_packed[base + k] = st[k];
}

// ----------------------------------------------------------------------------
// 2a) global histograms for ALL 4 digit positions (order-independent)
// ----------------------------------------------------------------------------
__global__ __launch_bounds__(SORT_THREADS)
void hist4_kernel(const unsigned* __restrict__ keys, int n)
{
    __shared__ unsigned h[4 * 256];
    #pragma unroll
    for (int k = threadIdx.x; k < 1024; k += 256) h[k] = 0;
    __syncthreads();

    int base = blockIdx.x * SORT_TILE;
    #pragma unroll 4
    for (int r = 0; r < SORT_EPT; r++) {
        int idx = base + r * SORT_THREADS + threadIdx.x;
        if (idx < n) {
            unsigned k = keys[idx];
            atomicAdd(&h[0*256 + (k         & 255u)], 1u);
            atomicAdd(&h[1*256 + ((k >> 8)  & 255u)], 1u);
            atomicAdd(&h[2*256 + ((k >> 16) & 255u)], 1u);
            atomicAdd(&h[3*256 + ((k >> 24)       )], 1u);
        }
    }
    __syncthreads();
    #pragma unroll
    for (int k = threadIdx.x; k < 1024; k += 256) {
        unsigned c = h[k];
        if (c) atomicAdd(&g_gh4[k], c);
    }
}

// 2b) exclusive scan of each pass's 256-bin histogram (1 block)
__global__ __launch_bounds__(256)
void scan4_kernel()
{
    __shared__ unsigned s[256];
    for (int p = 0; p < 4; p++) {
        unsigned v = g_gh4[p * 256 + threadIdx.x];
        s[threadIdx.x] = v;
        __syncthreads();
        for (int off = 1; off < 256; off <<= 1) {
            unsigned t = (threadIdx.x >= off) ? s[threadIdx.x - off] : 0u;
            __syncthreads();
            s[threadIdx.x] += t;
            __syncthreads();
        }
        g_base4[p * 256 + threadIdx.x] = s[threadIdx.x] - v;
        __syncthreads();
    }
}

// ----------------------------------------------------------------------------
// 2c) onesweep scatter: block hist -> publish AGG -> stable rank/exchange ->
//     decoupled lookback -> publish INC -> coalesced emit
// ----------------------------------------------------------------------------
__global__ __launch_bounds__(SORT_THREADS)
void scatter_os_kernel(const unsigned* __restrict__ kin,
                       const unsigned* __restrict__ vin,
                       unsigned* __restrict__ kout,
                       unsigned* __restrict__ vout,
                       int n, int shift, int pass)
{
    __shared__ unsigned       sHist[256];
    __shared__ unsigned       sGlob[256];   // scan scratch, then global run base
    __shared__ unsigned       sLoc[256];
    __shared__ unsigned       sBase[256];
    __shared__ unsigned short sCnt[8][256];
    __shared__ unsigned short sPre[8][256];
    __shared__ unsigned       sKey[SORT_TILE];
    __shared__ unsigned       sVal[SORT_TILE];

    int tid = threadIdx.x, warp = tid >> 5, lane = tid & 31;
    int bid = blockIdx.x;
    int base = bid * SORT_TILE;
    int m = n - base; if (m > SORT_TILE) m = SORT_TILE;
    unsigned ltmask = (1u << lane) - 1u;

    unsigned* lb = g_lb + (size_t)pass * (MAX_NB * 256);

    // --- block-local digit histogram ---
    sHist[tid] = 0;
    __syncthreads();
    #pragma unroll 4
    for (int r = 0; r < SORT_EPT; r++) {
        int idx = base + r * SORT_THREADS + tid;
        if (idx < n) atomicAdd(&sHist[(kin[idx] >> shift) & 255u], 1u);
    }
    __syncthreads();
    unsigned cnt = sHist[tid];

    // publish aggregate ASAP (block 0 publishes inclusive)
    atomicExch(&lb[(size_t)bid * 256 + tid],
               cnt | (bid == 0 ? INC_FLAG : AGG_FLAG));

    // --- local exclusive digit-start scan ---
    sGlob[tid] = cnt;
    __syncthreads();
    for (int off = 1; off < 256; off <<= 1) {
        unsigned t = (tid >= off) ? sGlob[tid - off] : 0u;
        __syncthreads();
        sGlob[tid] += t;
        __syncthreads();
    }
    unsigned loc = sGlob[tid] - cnt;
    sLoc[tid]  = loc;
    sBase[tid] = loc;

    // --- stable ranking into shared tile ---
    for (int r = 0; r < SORT_EPT; r++) {
        #pragma unroll
        for (int w = 0; w < 8; w++) sCnt[w][tid] = 0;
        __syncthreads();

        int idx = base + r * SORT_THREADS + tid;
        bool valid = (idx < n);
        unsigned key = 0, val = 0, digit = 0;
        if (valid) { key = kin[idx]; val = vin[idx]; digit = (key >> shift) & 255u; }

        unsigned vm    = __ballot_sync(0xffffffffu, valid);
        unsigned peers = __match_any_sync(0xffffffffu, digit) & vm;
        unsigned rank  = __popc(peers & ltmask);
        if (valid && rank == 0) sCnt[warp][digit] = (unsigned short)__popc(peers);
        __syncthreads();

        {
            unsigned acc = sBase[tid];
            #pragma unroll
            for (int w = 0; w < 8; w++) {
                unsigned c = sCnt[w][tid];
                sPre[w][tid] = (unsigned short)acc;
                acc += c;
            }
            sBase[tid] = acc;
        }
        __syncthreads();

        if (valid) {
            unsigned p = (unsigned)sPre[warp][digit] + rank;
            sKey[p] = key;
            sVal[p] = val;
        }
    }
    __syncthreads();

    // --- decoupled lookback (8-wide batched backward walk) ---
    unsigned excl = 0;
    if (bid > 0) {
        volatile unsigned* vlb = (volatile unsigned*)lb;
        int j = bid - 1;
        bool done = false;
        while (!done) {
            unsigned sv[8];
            int take = (j + 1 < 8) ? (j + 1) : 8;
            #pragma unroll
            for (int t = 0; t < 8; t++)
                if (t < take) sv[t] = vlb[(size_t)(j - t) * 256 + tid];
            for (int t = 0; t < take; t++) {
                unsigned v = sv[t];
                while (v < AGG_FLAG) v = vlb[(size_t)(j - t) * 256 + tid];
                excl += v & VAL_MASK;
                if (v >= INC_FLAG) { done = true; break; }
            }
            j -= take;
            if (j < 0) done = true;
        }
        atomicExch(&lb[(size_t)bid * 256 + tid], (excl + cnt) | INC_FLAG);
    }

    sGlob[tid] = g_base4[pass * 256 + tid] + excl;
    __syncthreads();

    // --- coalesced emit: digit runs contiguous locally and globally ---
    for (int j = tid; j < m; j += SORT_THREADS) {
        unsigned key = sKey[j];
        unsigned d = (key >> shift) & 255u;
        unsigned pos = sGlob[d] + ((unsigned)j - sLoc[d]);
        kout[pos] = key;
        vout[pos] = sVal[j];
    }
}

// ----------------------------------------------------------------------------
// 3) gather: out[r][c] = packed[idx[r]][c]
// ----------------------------------------------------------------------------
__global__ __launch_bounds__(256)
void gather_kernel(float* __restrict__ out, int total)
{
    int j = blockIdx.x * blockDim.x + threadIdx.x;
    if (j >= total) return;
    unsigned uj = (unsigned)j;
    unsigned r = uj / 21u;
    unsigned c = uj - r * 21u;
    unsigned src = g_valA[r];
    out[j] = g_packed[(size_t)src * NPAD + c];
}

// ----------------------------------------------------------------------------
extern "C" void kernel_launch(void* const* d_in, const int* in_sizes, int n_in,
                              void* d_out, int out_size)
{
    const float* pts  = (const float*)d_in[0];
    const float* cols = (const float*)d_in[1];
    const float* opa  = (const float*)d_in[2];
    const float* scl  = (const float*)d_in[3];
    const float* quat = (const float*)d_in[4];
    const float* V    = (const float*)d_in[5];
    const float* F    = (const float*)d_in[6];
    const float* tanx = (const float*)d_in[7];
    const float* tany = (const float*)d_in[8];
    const float* fx   = (const float*)d_in[9];
    const float* fy   = (const float*)d_in[10];
    const int*   wp   = (const int*)d_in[11];
    const int*   hp   = (const int*)d_in[12];
    float* out = (float*)d_out;

    int n = in_sizes[2];           // opacity has N elements
    if (n <= 0 || n > N_MAX) return;
    (void)n_in; (void)out_size;

    static unsigned *kA = nullptr, *kB = nullptr, *vA = nullptr, *vB = nullptr;
    static void *lbp = nullptr, *ghp = nullptr;
    if (!kA) {
        cudaGetSymbolAddress((void**)&kA, g_keyA);
        cudaGetSymbolAddress((void**)&kB, g_keyB);
        cudaGetSymbolAddress((void**)&vA, g_valA);
        cudaGetSymbolAddress((void**)&vB, g_valB);
        cudaGetSymbolAddress(&lbp, g_lb);
        cudaGetSymbolAddress(&ghp, g_gh4);
    }

    int nb = (n + SORT_TILE - 1) / SORT_TILE;

    // zero lookback state + global hists (graph-capturable memsets)
    cudaMemsetAsync(lbp, 0, sizeof(unsigned) * 4 * MAX_NB * 256);
    cudaMemsetAsync(ghp, 0, sizeof(unsigned) * 4 * 256);

    int prep_blocks = (n + 255) / 256;
    prep_kernel<<<prep_blocks, 256>>>(pts, cols, opa, scl, quat, V, F,
                                      tanx, tany, fx, fy, wp, hp, n);

    hist4_kernel<<<nb, SORT_THREADS>>>(kA, n);
    scan4_kernel<<<1, 256>>>();

    unsigned* kin = kA;  unsigned* vin = vA;
    unsigned* kout = kB; unsigned* vout = vB;
    for (int p = 0; p < 4; p++) {
        scatter_os_kernel<<<nb, SORT_THREADS>>>(kin, vin, kout, vout, n, p * 8, p);
        unsigned* tk = kin; kin = kout; kout = tk;
        unsigned* tv = vin; vin = vout; vout = tv;
    }
    // after 4 passes, sorted (key,val) are back in g_keyA/g_valA

    int total = n * NCOLS;
    int gather_blocks = (total + 255) / 256;
    gather_kernel<<<gather_blocks, 256>>>(out, total);
}